// round 1
// baseline (speedup 1.0000x reference)
#include <cuda_runtime.h>
#include <cuda_bf16.h>
#include <cstdint>

#define BSZ   128
#define SEQ   256
#define FDIM  512
#define EDIM  512
#define HEADS 8
#define BSROWS (BSZ*SEQ)          // 32768
#define MLPD  2048
#define MIN_POS 1e-6f

// ---------------- scratch (static device globals; no runtime allocation) ----
__device__ float g_xn  [(size_t)BSROWS*FDIM];   // layernormed input / reused for LN2
__device__ float g_xe  [(size_t)BSROWS*EDIM];   // L1-normalized embedding (constant over iters)
__device__ float g_h   [(size_t)BSROWS*EDIM];   // NNMF state
__device__ float g_u1  [(size_t)BSROWS*EDIM];   // intermediate u1 (also raw embed before norm)
__device__ float g_r   [(size_t)BSROWS*EDIM];   // reconstruction
__device__ float g_xres[(size_t)BSROWS*FDIM];   // x + attn residual
__device__ float g_mlp [(size_t)BSROWS*MLPD];   // MLP hidden

// ---------------- LayerNorm: warp per row (512) ------------------------------
__global__ __launch_bounds__(256) void ln_kernel(
    const float* __restrict__ x, const float* __restrict__ g,
    const float* __restrict__ b, float* __restrict__ out)
{
    int row  = blockIdx.x * 8 + (threadIdx.x >> 5);
    int lane = threadIdx.x & 31;
    const float* xr = x + (size_t)row * 512;
    float4 v[4];
    float s = 0.f, sq = 0.f;
#pragma unroll
    for (int w = 0; w < 4; w++) {
        v[w] = *(const float4*)&xr[w * 128 + lane * 4];
        s  += v[w].x + v[w].y + v[w].z + v[w].w;
        sq += v[w].x*v[w].x + v[w].y*v[w].y + v[w].z*v[w].z + v[w].w*v[w].w;
    }
#pragma unroll
    for (int off = 16; off > 0; off >>= 1) {
        s  += __shfl_xor_sync(0xffffffffu, s,  off);
        sq += __shfl_xor_sync(0xffffffffu, sq, off);
    }
    float mu   = s * (1.f / 512.f);
    float var  = sq * (1.f / 512.f) - mu * mu;
    float rstd = rsqrtf(var + 1e-5f);
    float* orow = out + (size_t)row * 512;
#pragma unroll
    for (int w = 0; w < 4; w++) {
        int c = w * 128 + lane * 4;
        float4 gv = *(const float4*)&g[c];
        float4 bv = *(const float4*)&b[c];
        float4 o;
        o.x = (v[w].x - mu) * rstd * gv.x + bv.x;
        o.y = (v[w].y - mu) * rstd * gv.y + bv.y;
        o.z = (v[w].z - mu) * rstd * gv.z + bv.z;
        o.w = (v[w].w - mu) * rstd * gv.w + bv.w;
        *(float4*)&orow[c] = o;
    }
}

// ---------------- per-64-group L1 normalize (warp per group) ----------------
__global__ __launch_bounds__(256) void l1norm64_kernel(
    const float* __restrict__ in, float* __restrict__ out)
{
    int grp  = blockIdx.x * 8 + (threadIdx.x >> 5);
    int lane = threadIdx.x & 31;
    size_t base = (size_t)grp * 64 + lane * 2;
    float2 v = *(const float2*)&in[base];
    float s = fabsf(v.x) + fabsf(v.y);
#pragma unroll
    for (int off = 16; off > 0; off >>= 1) s += __shfl_xor_sync(0xffffffffu, s, off);
    float inv = 1.f / fmaxf(s, 1e-12f);
    float2 o; o.x = v.x * inv; o.y = v.y * inv;
    *(float2*)&out[base] = o;
}

// ---------------- generic SGEMM  C[M,N] = A[M,K] @ W[N,K]^T + bias ----------
// EPI: 0 = clip(MIN_POS), 1 = +res, 2 = gelu(tanh)
__device__ __forceinline__ float gelu_tanh(float v) {
    float t = tanhf(0.7978845608028654f * (v + 0.044715f * v * v * v));
    return 0.5f * v * (1.f + t);
}

template <int EPI>
__global__ __launch_bounds__(256) void sgemm_kernel(
    const float* __restrict__ A, const float* __restrict__ W,
    const float* __restrict__ bias, const float* __restrict__ res,
    float* __restrict__ C, int N, int K)
{
    __shared__ float As[16][132];
    __shared__ float Ws[16][132];
    const int tid = threadIdx.x, tx = tid & 15, ty = tid >> 4;
    const int n0 = blockIdx.x * 128;
    const size_t m0 = (size_t)blockIdx.y * 128;

    float acc[8][8];
#pragma unroll
    for (int r = 0; r < 8; r++)
#pragma unroll
        for (int j = 0; j < 8; j++) acc[r][j] = 0.f;

    for (int kt = 0; kt < K; kt += 16) {
        __syncthreads();
#pragma unroll
        for (int q = 0; q < 2; q++) {
            int lin4 = tid * 2 + q;
            int row  = lin4 >> 2;
            int c4   = (lin4 & 3) << 2;
            float4 va = *(const float4*)&A[(m0 + row) * K + kt + c4];
            As[c4 + 0][row] = va.x; As[c4 + 1][row] = va.y;
            As[c4 + 2][row] = va.z; As[c4 + 3][row] = va.w;
            float4 vw = *(const float4*)&W[(size_t)(n0 + row) * K + kt + c4];
            Ws[c4 + 0][row] = vw.x; Ws[c4 + 1][row] = vw.y;
            Ws[c4 + 2][row] = vw.z; Ws[c4 + 3][row] = vw.w;
        }
        __syncthreads();
#pragma unroll
        for (int k = 0; k < 16; k++) {
            float4 a0 = *(const float4*)&As[k][ty * 4];
            float4 a1 = *(const float4*)&As[k][64 + ty * 4];
            float4 b0 = *(const float4*)&Ws[k][tx * 4];
            float4 b1 = *(const float4*)&Ws[k][64 + tx * 4];
            float av[8] = {a0.x, a0.y, a0.z, a0.w, a1.x, a1.y, a1.z, a1.w};
            float bv[8] = {b0.x, b0.y, b0.z, b0.w, b1.x, b1.y, b1.z, b1.w};
#pragma unroll
            for (int r = 0; r < 8; r++)
#pragma unroll
                for (int j = 0; j < 8; j++) acc[r][j] += av[r] * bv[j];
        }
    }

#pragma unroll
    for (int mi = 0; mi < 2; mi++)
#pragma unroll
        for (int ni = 0; ni < 2; ni++)
#pragma unroll
            for (int r = 0; r < 4; r++) {
                size_t m = m0 + mi * 64 + ty * 4 + r;
                int n = n0 + ni * 64 + tx * 4;
                float4 bi = *(const float4*)&bias[n];
                float vv[4];
#pragma unroll
                for (int j = 0; j < 4; j++) vv[j] = acc[mi * 4 + r][ni * 4 + j];
                vv[0] += bi.x; vv[1] += bi.y; vv[2] += bi.z; vv[3] += bi.w;
                if (EPI == 0) {
#pragma unroll
                    for (int j = 0; j < 4; j++) vv[j] = fmaxf(vv[j], MIN_POS);
                } else if (EPI == 1) {
                    float4 rr = *(const float4*)&res[m * N + n];
                    vv[0] += rr.x; vv[1] += rr.y; vv[2] += rr.z; vv[3] += rr.w;
                } else if (EPI == 2) {
#pragma unroll
                    for (int j = 0; j < 4; j++) vv[j] = gelu_tanh(vv[j]);
                }
                float4 o; o.x = vv[0]; o.y = vv[1]; o.z = vv[2]; o.w = vv[3];
                *(float4*)&C[m * N + n] = o;
            }
}

// ---------------- NNMF kernel A -----------------------------------------
// per (b, head, itile): t1 = Gw^T @ h  (128 x 64 over K=256)
//   r  = l1norm(clip(t1 @ lw))        -> g_r
//   u1 = (xe / r) @ lw^T              -> g_u1
__global__ __launch_bounds__(256) void nnmfA_kernel(
    const float* __restrict__ h, const float* __restrict__ gw,
    const float* __restrict__ lw, const float* __restrict__ xe,
    float* __restrict__ r_out, float* __restrict__ u1_out)
{
    extern __shared__ float sm[];
    float (*As)[128]  = (float(*)[128])(sm);           // 2048
    float (*Bs)[64]   = (float(*)[64])(sm + 2048);     // 1024
    float (*lws)[68]  = (float(*)[68])(sm + 3072);     // 4352
    float (*lwsT)[68] = (float(*)[68])(sm + 7424);     // 4352
    float (*Tst)[132] = (float(*)[132])(sm + 11776);   // 8448
    float* sums = sm + 20224;                           // 128  -> total 20352 floats

    const int tid = threadIdx.x, tx = tid & 15, ty = tid >> 4;
    const int i0 = blockIdx.x * 128, head = blockIdx.y, b = blockIdx.z;

    // local_w + transpose into smem
#pragma unroll
    for (int q = 0; q < 16; q++) {
        int idx = q * 256 + tid;
        int g = idx >> 6, f = idx & 63;
        float v = lw[idx];
        lws[g][f] = v;
        lwsT[f][g] = v;
    }

    const float* hb = h + (((size_t)b * SEQ) * HEADS + head) * 64;  // +o*512+g
    float acc[8][4];
#pragma unroll
    for (int r = 0; r < 8; r++)
#pragma unroll
        for (int j = 0; j < 4; j++) acc[r][j] = 0.f;

    for (int kt = 0; kt < SEQ; kt += 16) {
        __syncthreads();
#pragma unroll
        for (int q = 0; q < 2; q++) {
            int lin = (tid * 2 + q) * 4;
            int k = lin >> 7, m = lin & 127;
            *(float4*)&As[k][m] = *(const float4*)&gw[(kt + k) * SEQ + i0 + m];
        }
        {
            int lin = tid * 4;
            int k = lin >> 6, g = lin & 63;
            *(float4*)&Bs[k][g] = *(const float4*)&hb[(size_t)(kt + k) * 512 + g];
        }
        __syncthreads();
#pragma unroll
        for (int k = 0; k < 16; k++) {
            float4 a0 = *(const float4*)&As[k][ty * 4];
            float4 a1 = *(const float4*)&As[k][64 + ty * 4];
            float4 b0 = *(const float4*)&Bs[k][tx * 4];
            float av[8] = {a0.x, a0.y, a0.z, a0.w, a1.x, a1.y, a1.z, a1.w};
            float bv[4] = {b0.x, b0.y, b0.z, b0.w};
#pragma unroll
            for (int r = 0; r < 8; r++)
#pragma unroll
                for (int j = 0; j < 4; j++) acc[r][j] += av[r] * bv[j];
        }
    }
    __syncthreads();
    // store t1 transposed: Tst[g][i]
#pragma unroll
    for (int r = 0; r < 4; r++)
#pragma unroll
        for (int j = 0; j < 4; j++) {
            Tst[tx * 4 + j][ty * 4 + r]      = acc[r][j];
            Tst[tx * 4 + j][64 + ty * 4 + r] = acc[4 + r][j];
        }
    __syncthreads();

    // mix1: rc[i][f] = sum_g t1[i][g]*lw[g][f], clamp
    float racc[8][4];
#pragma unroll
    for (int r = 0; r < 8; r++)
#pragma unroll
        for (int j = 0; j < 4; j++) racc[r][j] = 0.f;
#pragma unroll 16
    for (int k = 0; k < 64; k++) {
        float4 a0 = *(const float4*)&Tst[k][ty * 4];
        float4 a1 = *(const float4*)&Tst[k][64 + ty * 4];
        float4 b0 = *(const float4*)&lws[k][tx * 4];
        float av[8] = {a0.x, a0.y, a0.z, a0.w, a1.x, a1.y, a1.z, a1.w};
        float bv[4] = {b0.x, b0.y, b0.z, b0.w};
#pragma unroll
        for (int r = 0; r < 8; r++)
#pragma unroll
            for (int j = 0; j < 4; j++) racc[r][j] += av[r] * bv[j];
    }
#pragma unroll
    for (int r = 0; r < 8; r++)
#pragma unroll
        for (int j = 0; j < 4; j++) racc[r][j] = fmaxf(racc[r][j], MIN_POS);

    // row sums across tx via shuffle (16-lane groups)
    float rp[8];
#pragma unroll
    for (int r = 0; r < 8; r++) rp[r] = racc[r][0] + racc[r][1] + racc[r][2] + racc[r][3];
#pragma unroll
    for (int off = 1; off < 16; off <<= 1)
#pragma unroll
        for (int r = 0; r < 8; r++) rp[r] += __shfl_xor_sync(0xffffffffu, rp[r], off);
    if (tx == 0) {
#pragma unroll
        for (int r = 0; r < 4; r++) {
            sums[ty * 4 + r]      = rp[r];
            sums[64 + ty * 4 + r] = rp[4 + r];
        }
    }
    __syncthreads();

    // r_out = rc/s ; xr = xe * s / rc, stored transposed into Tst[f][i]
    const size_t rowbase = (((size_t)b * SEQ + i0) * HEADS + head) * 64;
#pragma unroll
    for (int mi = 0; mi < 2; mi++)
#pragma unroll
        for (int r = 0; r < 4; r++) {
            int m = mi * 64 + ty * 4 + r;
            float s = sums[m];
            float4 xev = *(const float4*)&xe[rowbase + (size_t)m * 512 + tx * 4];
            float rc0 = racc[mi * 4 + r][0], rc1 = racc[mi * 4 + r][1];
            float rc2 = racc[mi * 4 + r][2], rc3 = racc[mi * 4 + r][3];
            float invs = 1.f / s;
            float4 rv; rv.x = rc0 * invs; rv.y = rc1 * invs; rv.z = rc2 * invs; rv.w = rc3 * invs;
            *(float4*)&r_out[rowbase + (size_t)m * 512 + tx * 4] = rv;
            Tst[tx * 4 + 0][m] = xev.x * s / rc0;
            Tst[tx * 4 + 1][m] = xev.y * s / rc1;
            Tst[tx * 4 + 2][m] = xev.z * s / rc2;
            Tst[tx * 4 + 3][m] = xev.w * s / rc3;
        }
    __syncthreads();

    // mix2: u1[i][g] = sum_f xr[i][f]*lw[g][f]
    float uacc[8][4];
#pragma unroll
    for (int r = 0; r < 8; r++)
#pragma unroll
        for (int j = 0; j < 4; j++) uacc[r][j] = 0.f;
#pragma unroll 16
    for (int k = 0; k < 64; k++) {
        float4 a0 = *(const float4*)&Tst[k][ty * 4];
        float4 a1 = *(const float4*)&Tst[k][64 + ty * 4];
        float4 b0 = *(const float4*)&lwsT[k][tx * 4];
        float av[8] = {a0.x, a0.y, a0.z, a0.w, a1.x, a1.y, a1.z, a1.w};
        float bv[4] = {b0.x, b0.y, b0.z, b0.w};
#pragma unroll
        for (int r = 0; r < 8; r++)
#pragma unroll
            for (int j = 0; j < 4; j++) uacc[r][j] += av[r] * bv[j];
    }
#pragma unroll
    for (int mi = 0; mi < 2; mi++)
#pragma unroll
        for (int r = 0; r < 4; r++) {
            int m = mi * 64 + ty * 4 + r;
            float4 o;
            o.x = uacc[mi * 4 + r][0]; o.y = uacc[mi * 4 + r][1];
            o.z = uacc[mi * 4 + r][2]; o.w = uacc[mi * 4 + r][3];
            *(float4*)&u1_out[rowbase + (size_t)m * 512 + tx * 4] = o;
        }
}

// ---------------- NNMF kernel B -----------------------------------------
// per (b, head, otile): u2 = Gw @ u1 ; h <- l1norm(clip(h * u2))
__global__ __launch_bounds__(256) void nnmfB_kernel(
    const float* __restrict__ u1, const float* __restrict__ gw,
    const float* __restrict__ h_in, float* __restrict__ h_out)
{
    __shared__ float As[16][132];
    __shared__ float Bs[16][64];
    __shared__ float sums[128];

    const int tid = threadIdx.x, tx = tid & 15, ty = tid >> 4;
    const int o0 = blockIdx.x * 128, head = blockIdx.y, b = blockIdx.z;

    const float* ub = u1 + (((size_t)b * SEQ) * HEADS + head) * 64;
    float acc[8][4];
#pragma unroll
    for (int r = 0; r < 8; r++)
#pragma unroll
        for (int j = 0; j < 4; j++) acc[r][j] = 0.f;

    for (int kt = 0; kt < SEQ; kt += 16) {
        __syncthreads();
#pragma unroll
        for (int q = 0; q < 2; q++) {
            int lin4 = tid * 2 + q;
            int row = lin4 >> 2;
            int c4 = (lin4 & 3) << 2;
            float4 v = *(const float4*)&gw[(o0 + row) * SEQ + kt + c4];
            As[c4 + 0][row] = v.x; As[c4 + 1][row] = v.y;
            As[c4 + 2][row] = v.z; As[c4 + 3][row] = v.w;
        }
        {
            int lin = tid * 4;
            int k = lin >> 6, g = lin & 63;
            *(float4*)&Bs[k][g] = *(const float4*)&ub[(size_t)(kt + k) * 512 + g];
        }
        __syncthreads();
#pragma unroll
        for (int k = 0; k < 16; k++) {
            float4 a0 = *(const float4*)&As[k][ty * 4];
            float4 a1 = *(const float4*)&As[k][64 + ty * 4];
            float4 b0 = *(const float4*)&Bs[k][tx * 4];
            float av[8] = {a0.x, a0.y, a0.z, a0.w, a1.x, a1.y, a1.z, a1.w};
            float bv[4] = {b0.x, b0.y, b0.z, b0.w};
#pragma unroll
            for (int r = 0; r < 8; r++)
#pragma unroll
                for (int j = 0; j < 4; j++) acc[r][j] += av[r] * bv[j];
        }
    }

    const size_t rowbase = (((size_t)b * SEQ + o0) * HEADS + head) * 64;
    float hv[8][4];
#pragma unroll
    for (int mi = 0; mi < 2; mi++)
#pragma unroll
        for (int r = 0; r < 4; r++) {
            int m = mi * 64 + ty * 4 + r;
            float4 hl = *(const float4*)&h_in[rowbase + (size_t)m * 512 + tx * 4];
            hv[mi * 4 + r][0] = fmaxf(hl.x * acc[mi * 4 + r][0], MIN_POS);
            hv[mi * 4 + r][1] = fmaxf(hl.y * acc[mi * 4 + r][1], MIN_POS);
            hv[mi * 4 + r][2] = fmaxf(hl.z * acc[mi * 4 + r][2], MIN_POS);
            hv[mi * 4 + r][3] = fmaxf(hl.w * acc[mi * 4 + r][3], MIN_POS);
        }
    float rp[8];
#pragma unroll
    for (int r = 0; r < 8; r++) rp[r] = hv[r][0] + hv[r][1] + hv[r][2] + hv[r][3];
#pragma unroll
    for (int off = 1; off < 16; off <<= 1)
#pragma unroll
        for (int r = 0; r < 8; r++) rp[r] += __shfl_xor_sync(0xffffffffu, rp[r], off);
    if (tx == 0) {
#pragma unroll
        for (int r = 0; r < 4; r++) {
            sums[ty * 4 + r]      = rp[r];
            sums[64 + ty * 4 + r] = rp[4 + r];
        }
    }
    __syncthreads();
#pragma unroll
    for (int mi = 0; mi < 2; mi++)
#pragma unroll
        for (int r = 0; r < 4; r++) {
            int m = mi * 64 + ty * 4 + r;
            float inv = 1.f / sums[m];
            float4 o;
            o.x = hv[mi * 4 + r][0] * inv; o.y = hv[mi * 4 + r][1] * inv;
            o.z = hv[mi * 4 + r][2] * inv; o.w = hv[mi * 4 + r][3] * inv;
            *(float4*)&h_out[rowbase + (size_t)m * 512 + tx * 4] = o;
        }
}

// ---------------- host launcher ------------------------------------------
extern "C" void kernel_launch(void* const* d_in, const int* in_sizes, int n_in,
                              void* d_out, int out_size)
{
    const float* x    = (const float*)d_in[0];
    const float* ew   = (const float*)d_in[1];
    const float* eb   = (const float*)d_in[2];
    const float* lw   = (const float*)d_in[3];
    const float* gw   = (const float*)d_in[4];
    const float* ow   = (const float*)d_in[5];
    const float* ob   = (const float*)d_in[6];
    const float* ln1g = (const float*)d_in[7];
    const float* ln1b = (const float*)d_in[8];
    const float* ln2g = (const float*)d_in[9];
    const float* ln2b = (const float*)d_in[10];
    const float* w1   = (const float*)d_in[11];
    const float* b1   = (const float*)d_in[12];
    const float* w2   = (const float*)d_in[13];
    const float* b2   = (const float*)d_in[14];
    const float* h0   = (const float*)d_in[15];
    float* out = (float*)d_out;

    float *xn, *xe, *h, *u1, *r, *xres, *mlp;
    cudaGetSymbolAddress((void**)&xn,   g_xn);
    cudaGetSymbolAddress((void**)&xe,   g_xe);
    cudaGetSymbolAddress((void**)&h,    g_h);
    cudaGetSymbolAddress((void**)&u1,   g_u1);
    cudaGetSymbolAddress((void**)&r,    g_r);
    cudaGetSymbolAddress((void**)&xres, g_xres);
    cudaGetSymbolAddress((void**)&mlp,  g_mlp);

    const int A_SMEM = 20352 * 4;  // bytes of dynamic smem for nnmfA
    cudaFuncSetAttribute(nnmfA_kernel, cudaFuncAttributeMaxDynamicSharedMemorySize, A_SMEM);

    // 1. LN1
    ln_kernel<<<BSROWS / 8, 256>>>(x, ln1g, ln1b, xn);
    // 2. embed + clip  (raw into u1 buffer)
    sgemm_kernel<0><<<dim3(EDIM / 128, BSROWS / 128), 256>>>(xn, ew, eb, nullptr, u1, EDIM, FDIM);
    // 3. per-head L1 normalize -> xe
    l1norm64_kernel<<<BSROWS * HEADS / 8, 256>>>(u1, xe);
    // 4. NNMF iterations
    for (int it = 0; it < 10; it++) {
        const float* hcur = (it == 0) ? h0 : h;
        nnmfA_kernel<<<dim3(2, HEADS, BSZ), 256, A_SMEM>>>(hcur, gw, lw, xe, r, u1);
        if (it < 9)
            nnmfB_kernel<<<dim3(2, HEADS, BSZ), 256>>>(u1, gw, hcur, h);
    }
    // 5. out projection + residual with x
    sgemm_kernel<1><<<dim3(FDIM / 128, BSROWS / 128), 256>>>(r, ow, ob, x, xres, FDIM, EDIM);
    // 6. LN2
    ln_kernel<<<BSROWS / 8, 256>>>(xres, ln2g, ln2b, xn);
    // 7. MLP up + gelu
    sgemm_kernel<2><<<dim3(MLPD / 128, BSROWS / 128), 256>>>(xn, w1, b1, nullptr, mlp, MLPD, FDIM);
    // 8. MLP down + residual -> out
    sgemm_kernel<1><<<dim3(FDIM / 128, BSROWS / 128), 256>>>(mlp, w2, b2, xres, out, FDIM, MLPD);
}